// round 5
// baseline (speedup 1.0000x reference)
#include <cuda_runtime.h>

#define S_LEN    2048
#define NBATCH   64
#define DIN      512
#define HDIM     512
#define NCTA     128
#define NTHREADS 512
#define KT       64
#define ASTRIDE  68            // 64 + 4 pad
#define ABUF     (64 * ASTRIDE)
#define NROWS    16            // gate rows per CTA (4 units x 4 gates)
#define KTOT     1024          // DIN + HDIM

// Software grid barrier state (persists across graph replays; gen0-relative)
__device__ unsigned g_bar_count = 0;
__device__ unsigned g_bar_gen   = 0;

__device__ __forceinline__ float fast_sigmoid(float x) {
    return 1.0f / (1.0f + __expf(-x));
}
__device__ __forceinline__ float fast_tanh(float x) {
    float ax = fabsf(x);
    float e  = __expf(-2.0f * ax);
    float t  = (1.0f - e) / (1.0f + e);
    return copysignf(t, x);
}

// packed dual-FMA: d.lo += a.lo*b.lo ; d.hi += a.hi*b.hi
__device__ __forceinline__ void ffma2(unsigned long long& d,
                                      unsigned long long a,
                                      unsigned long long b) {
    asm("fma.rn.f32x2 %0, %1, %2, %0;" : "+l"(d) : "l"(a), "l"(b));
}
__device__ __forceinline__ float pairsum(unsigned long long v) {
    float lo, hi;
    asm("mov.b64 {%0, %1}, %2;" : "=f"(lo), "=f"(hi) : "l"(v));
    return lo + hi;
}

__global__ __launch_bounds__(NTHREADS, 1)
void lstm_persistent(const float* __restrict__ x,
                     const float* __restrict__ Wih,
                     const float* __restrict__ Whh,
                     const float* __restrict__ bih,
                     const float* __restrict__ bhh,
                     float* __restrict__ out)
{
    extern __shared__ float sm[];
    // Wsm2: paired weights, ull[kp*16 + r] = (W[2kp][r], W[2kp+1][r]); 64 KB
    unsigned long long* Wsm2 = (unsigned long long*)sm;
    float* As   = sm + (KTOT / 2) * NROWS * 2;   // 4 x ABUF  (~69.6 KB)
    float* bsm  = As + 4 * ABUF;                 // [NROWS]
    unsigned* sgen0 = (unsigned*)(bsm + NROWS);

    const int tid = threadIdx.x;
    const int ct  = blockIdx.x;
    const int hid = tid >> 8;       // 0 = x half (warps 0-7), 1 = h half
    const int ht  = tid & 255;

    // GEMM mapping within a half: batches {j*16+bg}, rows rg*4..+3, k-slice ks
    const int bg = ht & 15;
    const int rg = (ht >> 4) & 3;
    const int ks = ht >> 6;         // 0..3, 16 k per tile each

    // Staging loader mapping (within half)
    const int lb = ht >> 2;
    const int kc = (ht & 3) * 4;

    // Elementwise mapping (low 256 threads): (batch eb, local unit eu)
    const int eb = tid >> 2;
    const int eu = tid & 3;
    float c_state = 0.0f;

    float* Ah   = As + hid * 2 * ABUF;   // this half's double buffer
    float* RedA = As;                    // 4 slices x 1024 floats (aliases bufs)
    float* RedB = As + 2 * ABUF;

    // ---- persistent weight slice -> SMEM (paired layout) ----
    for (int idx = tid; idx < NROWS * KTOT; idx += NTHREADS) {
        int r = idx >> 10;
        int k = idx & (KTOT - 1);
        int unit = r >> 2, gate = r & 3;
        int grow = gate * HDIM + ct * 4 + unit;
        float w = (k < DIN) ? Wih[grow * DIN + k] : Whh[grow * HDIM + (k - DIN)];
        ((float*)Wsm2)[(((k >> 1) * NROWS + r) << 1) | (k & 1)] = w;
    }
    if (tid < NROWS) {
        int unit = tid >> 2, gate = tid & 3;
        int grow = gate * HDIM + ct * 4 + unit;
        bsm[tid] = bih[grow] + bhh[grow];
    }
    if (tid == 0) *sgen0 = *((volatile unsigned*)&g_bar_gen);
    __syncthreads();
    const unsigned gen0 = *sgen0;

    float* hout = out;
    float* cout = out + (size_t)S_LEN * NBATCH * HDIM;

    for (int t = 0; t < S_LEN; ++t) {
        float* Red = hid ? RedB : RedA;

        if (hid == 1 && t == 0) {
            // h0 == 0: zero partials, no compute, no wait
            float4 z = make_float4(0.f, 0.f, 0.f, 0.f);
            for (int i = ht; i < 1024; i += 256)
                *(float4*)(RedB + 4 * i) = z;
        } else {
            if (hid == 1) {
                // split-phase grid barrier: WAIT here (overlapped with x half)
                if (ht == 0) {
                    unsigned target = gen0 + (unsigned)t;
                    while ((int)(*((volatile unsigned*)&g_bar_gen) - target) < 0) { }
                }
                asm volatile("bar.sync 2, 256;" ::: "memory");
            }
            const float* srcb = (hid == 0)
                ? x + (size_t)t * NBATCH * DIN
                : hout + (size_t)(t - 1) * NBATCH * HDIM;

            unsigned long long acc[4][4];
#pragma unroll
            for (int j = 0; j < 4; ++j)
#pragma unroll
                for (int r = 0; r < 4; ++r) acc[j][r] = 0ull;

            float4 ld0, ld1, ld2, ld3;

#define LOADT(TILE) do {                                                  \
                const float* _p = srcb + (size_t)lb * 512 + (TILE)*KT + kc; \
                ld0 = *(const float4*)(_p);                               \
                ld1 = *(const float4*)(_p + 16);                          \
                ld2 = *(const float4*)(_p + 32);                          \
                ld3 = *(const float4*)(_p + 48);                          \
            } while (0)
#define STORET(BUF) do {                                                  \
                float* _d = Ah + (BUF) * ABUF + lb * ASTRIDE + kc;        \
                *(float4*)(_d)      = ld0;                                \
                *(float4*)(_d + 16) = ld1;                                \
                *(float4*)(_d + 32) = ld2;                                \
                *(float4*)(_d + 48) = ld3;                                \
            } while (0)

            LOADT(0);
            STORET(0);
            asm volatile("bar.sync %0, 256;" :: "r"(hid + 1) : "memory");

            for (int tile = 0; tile < 8; ++tile) {
                const int cur = tile & 1;
                const bool more = (tile + 1 < 8);
                if (more) LOADT(tile + 1);

                const float* Abuf = Ah + cur * ABUF;
                const int kpb = (hid * 512 + tile * KT) >> 1;  // k-pair base

#pragma unroll
                for (int c = 0; c < 4; ++c) {
                    const int kof = ks * 16 + c * 4;
                    const unsigned long long* wp =
                        Wsm2 + (size_t)(kpb + (kof >> 1)) * NROWS + rg * 4;
                    ulonglong2 w00 = *(const ulonglong2*)(wp);       // kp0 r0,r1
                    ulonglong2 w01 = *(const ulonglong2*)(wp + 2);   // kp0 r2,r3
                    ulonglong2 w10 = *(const ulonglong2*)(wp + 16);  // kp1 r0,r1
                    ulonglong2 w11 = *(const ulonglong2*)(wp + 18);  // kp1 r2,r3

#pragma unroll
                    for (int j = 0; j < 4; ++j) {
                        ulonglong2 av =
                            *(const ulonglong2*)(Abuf + (j * 16 + bg) * ASTRIDE + kof);
                        ffma2(acc[j][0], av.x, w00.x);
                        ffma2(acc[j][1], av.x, w00.y);
                        ffma2(acc[j][2], av.x, w01.x);
                        ffma2(acc[j][3], av.x, w01.y);
                        ffma2(acc[j][0], av.y, w10.x);
                        ffma2(acc[j][1], av.y, w10.y);
                        ffma2(acc[j][2], av.y, w11.x);
                        ffma2(acc[j][3], av.y, w11.y);
                    }
                }

                if (more) STORET(cur ^ 1);
                asm volatile("bar.sync %0, 256;" :: "r"(hid + 1) : "memory");
            }
#undef LOADT
#undef STORET

            // partials -> Red[ks][b*16 + r] (aliases this half's buf0, done reading)
#pragma unroll
            for (int j = 0; j < 4; ++j) {
                float4 v;
                v.x = pairsum(acc[j][0]);
                v.y = pairsum(acc[j][1]);
                v.z = pairsum(acc[j][2]);
                v.w = pairsum(acc[j][3]);
                *(float4*)(Red + ks * 1024 + (j * 16 + bg) * 16 + rg * 4) = v;
            }
        }

        __syncthreads();   // both halves' partials ready

        if (tid < 256) {
            float4 g = make_float4(0.f, 0.f, 0.f, 0.f);
#pragma unroll
            for (int s = 0; s < 4; ++s) {
                float4 p = *(const float4*)(RedA + s * 1024 + 4 * tid);
                g.x += p.x; g.y += p.y; g.z += p.z; g.w += p.w;
                float4 q = *(const float4*)(RedB + s * 1024 + 4 * tid);
                g.x += q.x; g.y += q.y; g.z += q.z; g.w += q.w;
            }

            float gi = fast_sigmoid(g.x + bsm[eu * 4 + 0]);
            float gf = fast_sigmoid(g.y + bsm[eu * 4 + 1]);
            float gg = fast_tanh  (g.z + bsm[eu * 4 + 2]);
            float go = fast_sigmoid(g.w + bsm[eu * 4 + 3]);
            c_state = gf * c_state + gi * gg;
            float hval = go * fast_tanh(c_state);

            size_t o = (size_t)t * NBATCH * HDIM + (size_t)eb * HDIM + ct * 4 + eu;
            hout[o] = hval;
            cout[o] = c_state;
            __threadfence();
        }

        __syncthreads();   // h_t written + fenced by all writers

        // arrive-only; the wait lives in the h-half of step t+1
        if (tid == 0) {
            unsigned old = atomicAdd(&g_bar_count, 1u);
            if (old == (unsigned)(NCTA - 1)) {
                atomicExch(&g_bar_count, 0u);
                __threadfence();
                atomicAdd(&g_bar_gen, 1u);
            }
        }
    }
}

extern "C" void kernel_launch(void* const* d_in, const int* in_sizes, int n_in,
                              void* d_out, int out_size)
{
    const float* x   = (const float*)d_in[0];
    const float* Wih = (const float*)d_in[1];
    const float* Whh = (const float*)d_in[2];
    const float* bih = (const float*)d_in[3];
    const float* bhh = (const float*)d_in[4];
    float* out = (float*)d_out;

    // 64KB weights + 4x17.4KB A/Red + misc  (~135 KB): >114KB -> 1 CTA/SM,
    // so the 128-CTA persistent grid is fully co-resident (barrier safe).
    const int smem_bytes = ((KTOT / 2) * NROWS * 2 + 4 * ABUF + NROWS + 16) * 4;
    cudaFuncSetAttribute(lstm_persistent,
                         cudaFuncAttributeMaxDynamicSharedMemorySize, smem_bytes);

    lstm_persistent<<<NCTA, NTHREADS, smem_bytes>>>(x, Wih, Whh, bih, bhh, out);
}

// round 6
// speedup vs baseline: 1.0038x; 1.0038x over previous
#include <cuda_runtime.h>

#define S_LEN    2048
#define NBATCH   64
#define DIN      512
#define HDIM     512
#define NCTA     128
#define NTHREADS 512
#define KT       64
#define ASTRIDE  68            // 64 + 4 pad
#define ABUF     (64 * ASTRIDE)
#define NROWS    16            // gate rows per CTA (4 units x 4 gates)
#define KTOT     1024          // DIN + HDIM

// Software grid barrier state (persists across graph replays; gen0-relative)
__device__ unsigned g_bar_count = 0;
__device__ unsigned g_bar_gen   = 0;

__device__ __forceinline__ float fast_sigmoid(float x) {
    return 1.0f / (1.0f + __expf(-x));
}
__device__ __forceinline__ float fast_tanh(float x) {
    float ax = fabsf(x);
    float e  = __expf(-2.0f * ax);
    float t  = (1.0f - e) / (1.0f + e);
    return copysignf(t, x);
}

// packed dual-FMA: d.lo += a.lo*b.lo ; d.hi += a.hi*b.hi
__device__ __forceinline__ void ffma2(unsigned long long& d,
                                      unsigned long long a,
                                      unsigned long long b) {
    asm("fma.rn.f32x2 %0, %1, %2, %0;" : "+l"(d) : "l"(a), "l"(b));
}
__device__ __forceinline__ float pairsum(unsigned long long v) {
    float lo, hi;
    asm("mov.b64 {%0, %1}, %2;" : "=f"(lo), "=f"(hi) : "l"(v));
    return lo + hi;
}

__global__ __launch_bounds__(NTHREADS, 1)
void lstm_persistent(const float* __restrict__ x,
                     const float* __restrict__ Wih,
                     const float* __restrict__ Whh,
                     const float* __restrict__ bih,
                     const float* __restrict__ bhh,
                     float* __restrict__ out)
{
    extern __shared__ float sm[];
    // Wsm2: paired weights, ull[kp*16 + r] = (W[2kp][r], W[2kp+1][r]); 64 KB
    unsigned long long* Wsm2 = (unsigned long long*)sm;
    float* As   = sm + (KTOT / 2) * NROWS * 2;   // 4 x ABUF  (~69.6 KB)
    float* bsm  = As + 4 * ABUF;                 // [NROWS]
    unsigned* sgen0 = (unsigned*)(bsm + NROWS);

    const int tid = threadIdx.x;
    const int ct  = blockIdx.x;
    const int hid = tid >> 8;       // 0 = x half (warps 0-7), 1 = h half
    const int ht  = tid & 255;

    // GEMM mapping within a half: batches {j*16+bg}, rows rg*4..+3, k-slice ks
    const int bg = ht & 15;
    const int rg = (ht >> 4) & 3;
    const int ks = ht >> 6;         // 0..3, 16 k per tile each

    // Staging loader mapping (within half)
    const int lb = ht >> 2;
    const int kc = (ht & 3) * 4;

    // Elementwise mapping (low 256 threads): (batch eb, local unit eu)
    const int eb = tid >> 2;
    const int eu = tid & 3;
    float c_state = 0.0f;

    float* Ah   = As + hid * 2 * ABUF;   // this half's double buffer
    float* RedA = As;                    // 4 slices x 1024 floats (aliases bufs)
    float* RedB = As + 2 * ABUF;

    // ---- persistent weight slice -> SMEM (paired layout) ----
    for (int idx = tid; idx < NROWS * KTOT; idx += NTHREADS) {
        int r = idx >> 10;
        int k = idx & (KTOT - 1);
        int unit = r >> 2, gate = r & 3;
        int grow = gate * HDIM + ct * 4 + unit;
        float w = (k < DIN) ? Wih[grow * DIN + k] : Whh[grow * HDIM + (k - DIN)];
        ((float*)Wsm2)[(((k >> 1) * NROWS + r) << 1) | (k & 1)] = w;
    }
    if (tid < NROWS) {
        int unit = tid >> 2, gate = tid & 3;
        int grow = gate * HDIM + ct * 4 + unit;
        bsm[tid] = bih[grow] + bhh[grow];
    }
    if (tid == 0) *sgen0 = *((volatile unsigned*)&g_bar_gen);
    __syncthreads();
    const unsigned gen0 = *sgen0;

    float* hout = out;
    float* cout = out + (size_t)S_LEN * NBATCH * HDIM;

    for (int t = 0; t < S_LEN; ++t) {
        float* Red = hid ? RedB : RedA;

        if (hid == 1 && t == 0) {
            // h0 == 0: zero partials, no compute, no wait
            float4 z = make_float4(0.f, 0.f, 0.f, 0.f);
            for (int i = ht; i < 1024; i += 256)
                *(float4*)(RedB + 4 * i) = z;
        } else {
            if (hid == 1) {
                // split-phase grid barrier: WAIT here (overlapped with x half)
                if (ht == 0) {
                    unsigned target = gen0 + (unsigned)t;
                    while ((int)(*((volatile unsigned*)&g_bar_gen) - target) < 0) { }
                }
                asm volatile("bar.sync 2, 256;" ::: "memory");
            }
            const float* srcb = (hid == 0)
                ? x + (size_t)t * NBATCH * DIN
                : hout + (size_t)(t - 1) * NBATCH * HDIM;

            unsigned long long acc[4][4];
#pragma unroll
            for (int j = 0; j < 4; ++j)
#pragma unroll
                for (int r = 0; r < 4; ++r) acc[j][r] = 0ull;

            float4 ld0, ld1, ld2, ld3;

#define LOADT(TILE) do {                                                  \
                const float* _p = srcb + (size_t)lb * 512 + (TILE)*KT + kc; \
                ld0 = *(const float4*)(_p);                               \
                ld1 = *(const float4*)(_p + 16);                          \
                ld2 = *(const float4*)(_p + 32);                          \
                ld3 = *(const float4*)(_p + 48);                          \
            } while (0)
#define STORET(BUF) do {                                                  \
                float* _d = Ah + (BUF) * ABUF + lb * ASTRIDE + kc;        \
                *(float4*)(_d)      = ld0;                                \
                *(float4*)(_d + 16) = ld1;                                \
                *(float4*)(_d + 32) = ld2;                                \
                *(float4*)(_d + 48) = ld3;                                \
            } while (0)

            LOADT(0);
            STORET(0);
            asm volatile("bar.sync %0, 256;" :: "r"(hid + 1) : "memory");

            for (int tile = 0; tile < 8; ++tile) {
                const int cur = tile & 1;
                const bool more = (tile + 1 < 8);
                if (more) LOADT(tile + 1);

                const float* Abuf = Ah + cur * ABUF;
                const int kpb = (hid * 512 + tile * KT) >> 1;  // k-pair base

#pragma unroll
                for (int c = 0; c < 4; ++c) {
                    const int kof = ks * 16 + c * 4;
                    const unsigned long long* wp =
                        Wsm2 + (size_t)(kpb + (kof >> 1)) * NROWS + rg * 4;
                    ulonglong2 w00 = *(const ulonglong2*)(wp);       // kp0 r0,r1
                    ulonglong2 w01 = *(const ulonglong2*)(wp + 2);   // kp0 r2,r3
                    ulonglong2 w10 = *(const ulonglong2*)(wp + 16);  // kp1 r0,r1
                    ulonglong2 w11 = *(const ulonglong2*)(wp + 18);  // kp1 r2,r3

#pragma unroll
                    for (int j = 0; j < 4; ++j) {
                        ulonglong2 av =
                            *(const ulonglong2*)(Abuf + (j * 16 + bg) * ASTRIDE + kof);
                        ffma2(acc[j][0], av.x, w00.x);
                        ffma2(acc[j][1], av.x, w00.y);
                        ffma2(acc[j][2], av.x, w01.x);
                        ffma2(acc[j][3], av.x, w01.y);
                        ffma2(acc[j][0], av.y, w10.x);
                        ffma2(acc[j][1], av.y, w10.y);
                        ffma2(acc[j][2], av.y, w11.x);
                        ffma2(acc[j][3], av.y, w11.y);
                    }
                }

                if (more) STORET(cur ^ 1);
                asm volatile("bar.sync %0, 256;" :: "r"(hid + 1) : "memory");
            }
#undef LOADT
#undef STORET

            // partials -> Red[ks][b*16 + r] (aliases this half's buf0, done reading)
#pragma unroll
            for (int j = 0; j < 4; ++j) {
                float4 v;
                v.x = pairsum(acc[j][0]);
                v.y = pairsum(acc[j][1]);
                v.z = pairsum(acc[j][2]);
                v.w = pairsum(acc[j][3]);
                *(float4*)(Red + ks * 1024 + (j * 16 + bg) * 16 + rg * 4) = v;
            }
        }

        __syncthreads();   // both halves' partials ready

        if (tid < 256) {
            float4 g = make_float4(0.f, 0.f, 0.f, 0.f);
#pragma unroll
            for (int s = 0; s < 4; ++s) {
                float4 p = *(const float4*)(RedA + s * 1024 + 4 * tid);
                g.x += p.x; g.y += p.y; g.z += p.z; g.w += p.w;
                float4 q = *(const float4*)(RedB + s * 1024 + 4 * tid);
                g.x += q.x; g.y += q.y; g.z += q.z; g.w += q.w;
            }

            float gi = fast_sigmoid(g.x + bsm[eu * 4 + 0]);
            float gf = fast_sigmoid(g.y + bsm[eu * 4 + 1]);
            float gg = fast_tanh  (g.z + bsm[eu * 4 + 2]);
            float go = fast_sigmoid(g.w + bsm[eu * 4 + 3]);
            c_state = gf * c_state + gi * gg;
            float hval = go * fast_tanh(c_state);

            size_t o = (size_t)t * NBATCH * HDIM + (size_t)eb * HDIM + ct * 4 + eu;
            hout[o] = hval;
            cout[o] = c_state;
            __threadfence();
        }

        __syncthreads();   // h_t written + fenced by all writers

        // arrive-only; the wait lives in the h-half of step t+1
        if (tid == 0) {
            unsigned old = atomicAdd(&g_bar_count, 1u);
            if (old == (unsigned)(NCTA - 1)) {
                atomicExch(&g_bar_count, 0u);
                __threadfence();
                atomicAdd(&g_bar_gen, 1u);
            }
        }
    }
}

extern "C" void kernel_launch(void* const* d_in, const int* in_sizes, int n_in,
                              void* d_out, int out_size)
{
    const float* x   = (const float*)d_in[0];
    const float* Wih = (const float*)d_in[1];
    const float* Whh = (const float*)d_in[2];
    const float* bih = (const float*)d_in[3];
    const float* bhh = (const float*)d_in[4];
    float* out = (float*)d_out;

    // 64KB weights + 4x17.4KB A/Red + misc  (~135 KB): >114KB -> 1 CTA/SM,
    // so the 128-CTA persistent grid is fully co-resident (barrier safe).
    const int smem_bytes = ((KTOT / 2) * NROWS * 2 + 4 * ABUF + NROWS + 16) * 4;
    cudaFuncSetAttribute(lstm_persistent,
                         cudaFuncAttributeMaxDynamicSharedMemorySize, smem_bytes);

    lstm_persistent<<<NCTA, NTHREADS, smem_bytes>>>(x, Wih, Whh, bih, bhh, out);
}

// round 8
// speedup vs baseline: 1.4385x; 1.4331x over previous
#include <cuda_runtime.h>
#include <cstdint>

#define S_LEN    2048
#define NBATCH   64
#define DIN      512
#define HDIM     512
#define NCTA     128
#define NTHREADS 512
#define KT       64
#define ASTRIDE  68            // 64 + 4 pad
#define ABUF     (64 * ASTRIDE)
#define NROWS    16            // gate rows per CTA (4 units x 4 gates)
#define KTOT     1024
#define WFRAG_FLOATS (128 * 2 * 32 * 2)   // 128 kchunks x 2 ntiles x 32 lanes x float2
#define REDSTRIDE 24

__device__ unsigned g_bar_count = 0;
__device__ unsigned g_bar_gen   = 0;

__device__ __forceinline__ float fast_sigmoid(float x) {
    return 1.0f / (1.0f + __expf(-x));
}
__device__ __forceinline__ float fast_tanh(float x) {
    float ax = fabsf(x);
    float e  = __expf(-2.0f * ax);
    return copysignf((1.0f - e) / (1.0f + e), x);
}
__device__ __forceinline__ unsigned to_tf32(float f) {
    unsigned r;
    asm("cvt.rna.tf32.f32 %0, %1;" : "=r"(r) : "f"(f));
    return r;
}
__device__ __forceinline__ void mma_tf32(float* c, unsigned a0, unsigned a1,
                                         unsigned a2, unsigned a3,
                                         unsigned b0, unsigned b1) {
    asm("mma.sync.aligned.m16n8k8.row.col.f32.tf32.tf32.f32 "
        "{%0,%1,%2,%3}, {%4,%5,%6,%7}, {%8,%9}, {%0,%1,%2,%3};"
        : "+f"(c[0]), "+f"(c[1]), "+f"(c[2]), "+f"(c[3])
        : "r"(a0), "r"(a1), "r"(a2), "r"(a3), "r"(b0), "r"(b1));
}

__global__ __launch_bounds__(NTHREADS, 1)
void lstm_hmma(const float* __restrict__ x,
               const float* __restrict__ Wih,
               const float* __restrict__ Whh,
               const float* __restrict__ bih,
               const float* __restrict__ bhh,
               float* __restrict__ out)
{
    extern __shared__ float sm[];
    float* Wfrag = sm;                       // 64 KB, B-fragment order (tf32 bits)
    float* As    = sm + WFRAG_FLOATS;        // 4 x ABUF (x: buf0,1; h: buf2,3)
    float* bsm   = As + 4 * ABUF;            // [16]
    unsigned* sgen0 = (unsigned*)(bsm + NROWS);

    const int tid  = threadIdx.x;
    const int ct   = blockIdx.x;
    const int hid  = tid >> 8;               // 0 = x half, 1 = h half
    const int ht   = tid & 255;
    const int lane = tid & 31;
    const int whf  = ht >> 5;                // warp within half
    const int mt   = whf & 3;                // m-tile: batches mt*16..+15
    const int ks   = whf >> 2;               // k-slice within each staged tile

    // staging mapping (same as R3)
    const int lb = ht >> 2;
    const int kc = (ht & 3) * 4;

    // epilogue mapping (low 256 threads): batch eb, local unit eu
    const int eb = tid >> 2;
    const int eu = tid & 3;
    float c_state = 0.0f;

    float* Ah  = As + hid * 2 * ABUF;        // this half's double buffer
    // Red slices live in each half's OWN buffer region (written post-mma only)
    // slice s = hid*2 + ks at As + hid*2*ABUF + ks*1536, layout [64][REDSTRIDE]

    // ---- W -> SMEM in exact B-fragment order, tf32 (one-time) ----
    // slot s: kcg = s>>6, nt = (s>>5)&1, lane l = s&31
    //   n (local row) = nt*8 + (l>>2); k0 = kcg*8 + (l&3); k1 = k0 + 4
    //   local row r = unit*4+gate -> global row = gate*512 + ct*4 + unit
    for (int s = tid; s < 128 * 64; s += NTHREADS) {
        int kcg = s >> 6, nt = (s >> 5) & 1, l = s & 31;
        int r = nt * 8 + (l >> 2);
        int grow = (r & 3) * HDIM + ct * 4 + (r >> 2);
        int k0 = kcg * 8 + (l & 3);
        int k1 = k0 + 4;
        float w0 = (k0 < DIN) ? Wih[grow * DIN + k0] : Whh[grow * HDIM + (k0 - DIN)];
        float w1 = (k1 < DIN) ? Wih[grow * DIN + k1] : Whh[grow * HDIM + (k1 - DIN)];
        ((unsigned*)Wfrag)[2 * s]     = to_tf32(w0);
        ((unsigned*)Wfrag)[2 * s + 1] = to_tf32(w1);
    }
    if (tid < NROWS) {
        int grow = (tid & 3) * HDIM + ct * 4 + (tid >> 2);
        bsm[tid] = bih[grow] + bhh[grow];
    }
    if (tid == 0) *sgen0 = *((volatile unsigned*)&g_bar_gen);
    __syncthreads();
    const unsigned gen0 = *sgen0;

    float* hout = out;
    float* cout = out + (size_t)S_LEN * NBATCH * HDIM;

    for (int t = 0; t < S_LEN; ++t) {
        if (hid == 1 && t == 0) {
            // h0 == 0: zero this half's 2 Red slices (3072 floats)
            float4 z = make_float4(0.f, 0.f, 0.f, 0.f);
            for (int i = ht; i < 768; i += 256)
                *(float4*)(As + 2 * ABUF + 4 * i) = z;
        } else {
            if (hid == 1) {
                if (ht == 0) {
                    unsigned target = gen0 + (unsigned)t;
                    while ((int)(*((volatile unsigned*)&g_bar_gen) - target) < 0) { }
                }
                asm volatile("bar.sync 2, 256;" ::: "memory");
            }
            const float* srcb = (hid == 0)
                ? x + (size_t)t * NBATCH * DIN
                : hout + (size_t)(t - 1) * NBATCH * HDIM;

            float acc[2][2][4];     // [ntile][parity][c0..c3]
#pragma unroll
            for (int n = 0; n < 2; ++n)
#pragma unroll
                for (int p = 0; p < 2; ++p)
#pragma unroll
                    for (int q = 0; q < 4; ++q) acc[n][p][q] = 0.f;

            float4 ld0, ld1, ld2, ld3;
#define LOADT(TILE) do {                                                  \
                const float* _p = srcb + (size_t)lb * 512 + (TILE)*KT + kc; \
                ld0 = *(const float4*)(_p);                               \
                ld1 = *(const float4*)(_p + 16);                          \
                ld2 = *(const float4*)(_p + 32);                          \
                ld3 = *(const float4*)(_p + 48);                          \
            } while (0)
#define CVT4(F) make_uint4(to_tf32((F).x), to_tf32((F).y), to_tf32((F).z), to_tf32((F).w))
#define STORET(BUF) do {                                                  \
                unsigned* _d = (unsigned*)(Ah + (BUF) * ABUF) + lb * ASTRIDE + kc; \
                *(uint4*)(_d)      = CVT4(ld0);                           \
                *(uint4*)(_d + 16) = CVT4(ld1);                           \
                *(uint4*)(_d + 32) = CVT4(ld2);                           \
                *(uint4*)(_d + 48) = CVT4(ld3);                           \
            } while (0)

            LOADT(0);
            STORET(0);
            asm volatile("bar.sync %0, 256;" :: "r"(hid + 1) : "memory");

            const int ra = mt * 16 + (lane >> 2);       // A frag base row
            const uint2* Wf = (const uint2*)Wfrag;

            for (int tile = 0; tile < 8; ++tile) {
                const int cur = tile & 1;
                const bool more = (tile + 1 < 8);
                if (more) LOADT(tile + 1);

                const unsigned* Ab = (const unsigned*)(Ah + cur * ABUF);
#pragma unroll
                for (int i = 0; i < 4; ++i) {
                    const int ck  = ks * 4 + i;              // chunk in tile
                    const int kcg = hid * 64 + tile * 8 + ck;
                    const int ka  = ck * 8 + (lane & 3);
                    unsigned a0 = Ab[ra * ASTRIDE + ka];
                    unsigned a1 = Ab[(ra + 8) * ASTRIDE + ka];
                    unsigned a2 = Ab[ra * ASTRIDE + ka + 4];
                    unsigned a3 = Ab[(ra + 8) * ASTRIDE + ka + 4];
#pragma unroll
                    for (int nt = 0; nt < 2; ++nt) {
                        uint2 b = Wf[kcg * 64 + nt * 32 + lane];
                        mma_tf32(acc[nt][i & 1], a0, a1, a2, a3, b.x, b.y);
                    }
                }
                if (more) STORET(cur ^ 1);
                asm volatile("bar.sync %0, 256;" :: "r"(hid + 1) : "memory");
            }
#undef LOADT
#undef STORET
#undef CVT4

            // ---- partials -> this half's Red slice (own buffers, reads done) ----
            float* Rp = As + hid * 2 * ABUF + ks * 1536;
            const int rr = mt * 16 + (lane >> 2);
#pragma unroll
            for (int nt = 0; nt < 2; ++nt) {
                const int cc = nt * 8 + 2 * (lane & 3);
                float2 v01, v23;
                v01.x = acc[nt][0][0] + acc[nt][1][0];
                v01.y = acc[nt][0][1] + acc[nt][1][1];
                v23.x = acc[nt][0][2] + acc[nt][1][2];
                v23.y = acc[nt][0][3] + acc[nt][1][3];
                *(float2*)(Rp + rr * REDSTRIDE + cc)       = v01;
                *(float2*)(Rp + (rr + 8) * REDSTRIDE + cc) = v23;
            }
        }

        __syncthreads();   // all 4 Red slices ready

        if (tid < 256) {
            float g[4];
#pragma unroll
            for (int gg2 = 0; gg2 < 4; ++gg2) g[gg2] = bsm[eu * 4 + gg2];
#pragma unroll
            for (int s = 0; s < 4; ++s) {
                const float* Rp = As + (s >> 1) * 2 * ABUF + (s & 1) * 1536
                                  + eb * REDSTRIDE + eu * 4;
                g[0] += Rp[0]; g[1] += Rp[1]; g[2] += Rp[2]; g[3] += Rp[3];
            }
            float gi = fast_sigmoid(g[0]);
            float gf = fast_sigmoid(g[1]);
            float gg = fast_tanh  (g[2]);
            float go = fast_sigmoid(g[3]);
            c_state = gf * c_state + gi * gg;
            float hval = go * fast_tanh(c_state);

            size_t o = (size_t)t * NBATCH * HDIM + (size_t)eb * HDIM + ct * 4 + eu;
            hout[o] = hval;
            cout[o] = c_state;
            __threadfence();
        }

        __syncthreads();   // h_t written + fenced

        // arrive-only; wait lives in the h-half of step t+1
        if (tid == 0) {
            unsigned old = atomicAdd(&g_bar_count, 1u);
            if (old == (unsigned)(NCTA - 1)) {
                atomicExch(&g_bar_count, 0u);
                __threadfence();
                atomicAdd(&g_bar_gen, 1u);
            }
        }
    }
}

extern "C" void kernel_launch(void* const* d_in, const int* in_sizes, int n_in,
                              void* d_out, int out_size)
{
    const float* x   = (const float*)d_in[0];
    const float* Wih = (const float*)d_in[1];
    const float* Whh = (const float*)d_in[2];
    const float* bih = (const float*)d_in[3];
    const float* bhh = (const float*)d_in[4];
    float* out = (float*)d_out;

    // 64KB Wfrag + 69.6KB A/Red + misc ~ 135.3KB -> 1 CTA/SM (co-residency safe)
    const int smem_bytes = (WFRAG_FLOATS + 4 * ABUF + NROWS + 16) * 4;
    cudaFuncSetAttribute(lstm_hmma,
                         cudaFuncAttributeMaxDynamicSharedMemorySize, smem_bytes);

    lstm_hmma<<<NCTA, NTHREADS, smem_bytes>>>(x, Wih, Whh, bih, bhh, out);
}

// round 9
// speedup vs baseline: 1.8903x; 1.3140x over previous
#include <cuda_runtime.h>
#include <cstdint>

#define S_LEN    2048
#define NBATCH   64
#define DIN      512
#define HDIM     512
#define NCTA     128
#define KTOT     1024

// ---- 1 GB x-projection scratch: xp[t][ct][b][16] ----
__device__ float g_xp[(size_t)S_LEN * 128 * 64 * 16];

__device__ unsigned g_bar_count = 0;
__device__ unsigned g_bar_gen   = 0;

__device__ __forceinline__ float fast_sigmoid(float x) {
    return 1.0f / (1.0f + __expf(-x));
}
__device__ __forceinline__ float fast_tanh(float x) {
    float ax = fabsf(x);
    float e  = __expf(-2.0f * ax);
    return copysignf((1.0f - e) / (1.0f + e), x);
}
__device__ __forceinline__ unsigned to_tf32(float f) {
    unsigned r;
    asm("cvt.rna.tf32.f32 %0, %1;" : "=r"(r) : "f"(f));
    return r;
}
__device__ __forceinline__ void mma_tf32(float* c, unsigned a0, unsigned a1,
                                         unsigned a2, unsigned a3,
                                         unsigned b0, unsigned b1) {
    asm("mma.sync.aligned.m16n8k8.row.col.f32.tf32.tf32.f32 "
        "{%0,%1,%2,%3}, {%4,%5,%6,%7}, {%8,%9}, {%0,%1,%2,%3};"
        : "+f"(c[0]), "+f"(c[1]), "+f"(c[2]), "+f"(c[3])
        : "r"(a0), "r"(a1), "r"(a2), "r"(a3), "r"(b0), "r"(b1));
}

// gate-row scatter: n in [0,2048) -> W row. ct=n>>4, r=n&15, gate=r&3, unit slot r>>2
__device__ __forceinline__ int grow_of(int n) {
    return (n & 3) * HDIM + (n >> 4) * 4 + ((n >> 2) & 3);
}

// ======================= Phase 1: xp = x @ W_ih^T =======================
// C[M=131072, N=2048], K=512. CTA tile 128x128, K chunks of 64 (single buffer).
__global__ __launch_bounds__(256, 2)
void lstm_xproj(const float* __restrict__ x, const float* __restrict__ Wih)
{
    extern __shared__ float sm1[];
    float* At = sm1;              // 128 x 68
    float* Bt = sm1 + 128 * 68;   // 128 x 68

    const int tid  = threadIdx.x;
    const int lane = tid & 31;
    const int w    = tid >> 5;
    const int mw   = w & 3;       // warp m-block: 32 rows
    const int nw   = w >> 2;      // warp n-block: 64 cols
    const int ntile = blockIdx.x & 15;          // ntile-fastest: x reused in L2
    const int mtile = blockIdx.x >> 4;
    const int Mb = mtile * 128, Nb = ntile * 128;

    const int lb = tid >> 2;
    const int kc = (tid & 3) * 4;

    float acc[2][8][4];
#pragma unroll
    for (int a = 0; a < 2; ++a)
#pragma unroll
        for (int b = 0; b < 8; ++b)
#pragma unroll
            for (int q = 0; q < 4; ++q) acc[a][b][q] = 0.f;

    for (int ch = 0; ch < 8; ++ch) {
        __syncthreads();
#pragma unroll
        for (int p = 0; p < 2; ++p) {
            int row = p * 64 + lb;
            const float* xs = x + (size_t)(Mb + row) * 512 + ch * 64 + kc;
            unsigned* da = (unsigned*)At + row * 68 + kc;
            int n = Nb + row;
            const float* ws = Wih + (size_t)grow_of(n) * 512 + ch * 64 + kc;
            unsigned* db = (unsigned*)Bt + row * 68 + kc;
#pragma unroll
            for (int c4 = 0; c4 < 4; ++c4) {
                float4 f = *(const float4*)(xs + c4 * 16);
                *(uint4*)(da + c4 * 16) = make_uint4(to_tf32(f.x), to_tf32(f.y),
                                                     to_tf32(f.z), to_tf32(f.w));
                float4 g = *(const float4*)(ws + c4 * 16);
                *(uint4*)(db + c4 * 16) = make_uint4(to_tf32(g.x), to_tf32(g.y),
                                                     to_tf32(g.z), to_tf32(g.w));
            }
        }
        __syncthreads();

        const unsigned* A = (const unsigned*)At;
        const unsigned* B = (const unsigned*)Bt;
#pragma unroll
        for (int i = 0; i < 8; ++i) {
            const int ka = i * 8 + (lane & 3);
            unsigned a[2][4];
#pragma unroll
            for (int m2 = 0; m2 < 2; ++m2) {
                int rb = mw * 32 + m2 * 16 + (lane >> 2);
                a[m2][0] = A[rb * 68 + ka];
                a[m2][1] = A[(rb + 8) * 68 + ka];
                a[m2][2] = A[rb * 68 + ka + 4];
                a[m2][3] = A[(rb + 8) * 68 + ka + 4];
            }
#pragma unroll
            for (int nt = 0; nt < 8; ++nt) {
                int nb = nw * 64 + nt * 8 + (lane >> 2);
                unsigned b0 = B[nb * 68 + ka];
                unsigned b1 = B[nb * 68 + ka + 4];
                mma_tf32(acc[0][nt], a[0][0], a[0][1], a[0][2], a[0][3], b0, b1);
                mma_tf32(acc[1][nt], a[1][0], a[1][1], a[1][2], a[1][3], b0, b1);
            }
        }
    }

    // scatter C -> xp[t][ct][b][r]
#pragma unroll
    for (int m2 = 0; m2 < 2; ++m2) {
#pragma unroll
        for (int nt = 0; nt < 8; ++nt) {
            int row0 = Mb + mw * 32 + m2 * 16 + (lane >> 2);
            int n    = Nb + nw * 64 + nt * 8 + 2 * (lane & 3);
            int t = row0 >> 6, b = row0 & 63;
            size_t idx = (((size_t)t * 128 + (n >> 4)) * 64 + b) * 16 + (n & 15);
            *(float2*)(g_xp + idx)       = make_float2(acc[m2][nt][0], acc[m2][nt][1]);
            *(float2*)(g_xp + idx + 128) = make_float2(acc[m2][nt][2], acc[m2][nt][3]);
        }
    }
}

// ======================= Phase 2: persistent recurrence =======================
// SMEM float offsets
#define WF_OFF   0                    // 8192 floats (4096 uint2 B-frags, Whh)
#define HB_OFF   8192                 // 8 subtiles x 64 x 68 = 34816
#define RED_OFF  (HB_OFF + 34816)     // 4 x 1536 = 6144
#define BSM_OFF  (RED_OFF + 6144)     // 16
#define SG_OFF   (BSM_OFF + 16)
#define SM2_FLOATS (SG_OFF + 4)

__global__ __launch_bounds__(512, 1)
void lstm_rec(const float* __restrict__ Whh,
              const float* __restrict__ bih,
              const float* __restrict__ bhh,
              float* __restrict__ out)
{
    extern __shared__ float sm[];
    float* Wf  = sm + WF_OFF;
    float* Hb  = sm + HB_OFF;
    float* Red = sm + RED_OFF;
    float* bsm = sm + BSM_OFF;
    unsigned* sgen0 = (unsigned*)(sm + SG_OFF);

    const int tid  = threadIdx.x;
    const int lane = tid & 31;
    const int wid  = tid >> 5;
    const int ct   = blockIdx.x;
    const int mt   = wid & 3;          // batches mt*16..+15
    const int ks   = wid >> 2;         // k-slice: subtiles 2ks, 2ks+1

    // h staging mapping: 512 threads cover 64 x 512
    const int hb2 = tid >> 8;
    const int lb  = (tid & 255) >> 2;
    const int kc  = (tid & 3) * 4;

    // epilogue mapping (tid < 256)
    const int eb = tid >> 2;
    const int eu = tid & 3;
    float c_state = 0.0f;

    // ---- one-time: Whh B-fragments (tf32) + biases ----
    for (int s = tid; s < 4096; s += 512) {
        int kcg = s >> 6, nt = (s >> 5) & 1, l = s & 31;
        int r = nt * 8 + (l >> 2);
        int grow = (r & 3) * HDIM + ct * 4 + (r >> 2);
        int k0 = kcg * 8 + (l & 3);
        ((unsigned*)Wf)[2 * s]     = to_tf32(Whh[(size_t)grow * 512 + k0]);
        ((unsigned*)Wf)[2 * s + 1] = to_tf32(Whh[(size_t)grow * 512 + k0 + 4]);
    }
    if (tid < 16) {
        int grow = (tid & 3) * HDIM + ct * 4 + (tid >> 2);
        bsm[tid] = bih[grow] + bhh[grow];
    }
    if (tid == 0) *sgen0 = *((volatile unsigned*)&g_bar_gen);
    __syncthreads();
    const unsigned gen0 = *sgen0;

    float* hout = out;
    float* cout = out + (size_t)S_LEN * NBATCH * HDIM;

    for (int t = 0; t < S_LEN; ++t) {
        // prefetch this CTA's x-projection slice (independent of h)
        float4 xpv;
        if (tid < 256)
            xpv = *(const float4*)(g_xp + (((size_t)t * 128 + ct) * 64 + eb) * 16 + eu * 4);

        if (t > 0) {
            if (tid == 0) {
                unsigned target = gen0 + (unsigned)t;
                while ((int)(*((volatile unsigned*)&g_bar_gen) - target) < 0) { }
            }
            __syncthreads();

            // ---- stage full h_{t-1}: 8 subtiles of 64x64, stride 68 ----
            const float* hbase = hout + (size_t)(t - 1) * (NBATCH * HDIM);
#pragma unroll
            for (int i = 0; i < 4; ++i) {
                int st = hb2 * 4 + i;
                const float* sp = hbase + (size_t)lb * 512 + st * 64 + kc;
                unsigned* dp = (unsigned*)(Hb + st * 4352) + lb * 68 + kc;
#pragma unroll
                for (int c4 = 0; c4 < 4; ++c4) {
                    float4 f = *(const float4*)(sp + c4 * 16);
                    *(uint4*)(dp + c4 * 16) = make_uint4(to_tf32(f.x), to_tf32(f.y),
                                                         to_tf32(f.z), to_tf32(f.w));
                }
            }
            __syncthreads();

            // ---- h GEMM: warp (mt, ks), K slice 128 ----
            float acc[2][2][4];
#pragma unroll
            for (int n = 0; n < 2; ++n)
#pragma unroll
                for (int p = 0; p < 2; ++p)
#pragma unroll
                    for (int q = 0; q < 4; ++q) acc[n][p][q] = 0.f;

            const uint2* Wfu = (const uint2*)Wf;
#pragma unroll
            for (int st2 = 0; st2 < 2; ++st2) {
                const int st = ks * 2 + st2;
                const unsigned* Ab = (const unsigned*)(Hb + st * 4352);
#pragma unroll
                for (int i = 0; i < 8; ++i) {
                    const int ka = i * 8 + (lane & 3);
                    const int ra = mt * 16 + (lane >> 2);
                    unsigned a0 = Ab[ra * 68 + ka];
                    unsigned a1 = Ab[(ra + 8) * 68 + ka];
                    unsigned a2 = Ab[ra * 68 + ka + 4];
                    unsigned a3 = Ab[(ra + 8) * 68 + ka + 4];
                    const int kcg = st * 8 + i;
#pragma unroll
                    for (int nt = 0; nt < 2; ++nt) {
                        uint2 b = Wfu[kcg * 64 + nt * 32 + lane];
                        mma_tf32(acc[nt][i & 1], a0, a1, a2, a3, b.x, b.y);
                    }
                }
            }

            // partials -> Red[ks] : [64][24]
            float* Rp = Red + ks * 1536;
            const int rr = mt * 16 + (lane >> 2);
#pragma unroll
            for (int nt = 0; nt < 2; ++nt) {
                const int cc = nt * 8 + 2 * (lane & 3);
                *(float2*)(Rp + rr * 24 + cc) =
                    make_float2(acc[nt][0][0] + acc[nt][1][0],
                                acc[nt][0][1] + acc[nt][1][1]);
                *(float2*)(Rp + (rr + 8) * 24 + cc) =
                    make_float2(acc[nt][0][2] + acc[nt][1][2],
                                acc[nt][0][3] + acc[nt][1][3]);
            }
        }

        __syncthreads();

        if (tid < 256) {
            float g[4];
#pragma unroll
            for (int j = 0; j < 4; ++j) g[j] = bsm[eu * 4 + j];
            g[0] += xpv.x; g[1] += xpv.y; g[2] += xpv.z; g[3] += xpv.w;
            if (t > 0) {
#pragma unroll
                for (int s = 0; s < 4; ++s) {
                    const float4 p = *(const float4*)(Red + s * 1536 + eb * 24 + eu * 4);
                    g[0] += p.x; g[1] += p.y; g[2] += p.z; g[3] += p.w;
                }
            }
            float gi = fast_sigmoid(g[0]);
            float gf = fast_sigmoid(g[1]);
            float gg = fast_tanh  (g[2]);
            float go = fast_sigmoid(g[3]);
            c_state = gf * c_state + gi * gg;
            float hval = go * fast_tanh(c_state);

            size_t o = (size_t)t * (NBATCH * HDIM) + (size_t)eb * HDIM + ct * 4 + eu;
            hout[o] = hval;
            cout[o] = c_state;
            __threadfence();
        }

        __syncthreads();

        if (tid == 0) {
            unsigned old = atomicAdd(&g_bar_count, 1u);
            if (old == (unsigned)(NCTA - 1)) {
                atomicExch(&g_bar_count, 0u);
                __threadfence();
                atomicAdd(&g_bar_gen, 1u);
            }
        }
    }
}

extern "C" void kernel_launch(void* const* d_in, const int* in_sizes, int n_in,
                              void* d_out, int out_size)
{
    const float* x   = (const float*)d_in[0];
    const float* Wih = (const float*)d_in[1];
    const float* Whh = (const float*)d_in[2];
    const float* bih = (const float*)d_in[3];
    const float* bhh = (const float*)d_in[4];
    float* out = (float*)d_out;

    const int sm1_bytes = 2 * 128 * 68 * 4;          // 69.6 KB
    cudaFuncSetAttribute(lstm_xproj,
                         cudaFuncAttributeMaxDynamicSharedMemorySize, sm1_bytes);
    const int sm2_bytes = SM2_FLOATS * 4;            // ~196.7 KB -> 1 CTA/SM
    cudaFuncSetAttribute(lstm_rec,
                         cudaFuncAttributeMaxDynamicSharedMemorySize, sm2_bytes);

    lstm_xproj<<<16384, 256, sm1_bytes>>>(x, Wih);
    lstm_rec<<<NCTA, 512, sm2_bytes>>>(Whh, bih, bhh, out);
}

// round 12
// speedup vs baseline: 2.2216x; 1.1753x over previous
#include <cuda_runtime.h>
#include <cstdint>

#define S_LEN    2048
#define NBATCH   64
#define DIN      512
#define HDIM     512
#define NCTA     128

// ---- 1 GB x-projection scratch: xp[t][ct][b][16] ----
__device__ float g_xp[(size_t)S_LEN * 128 * 64 * 16];

// monotonic grid-barrier counter (64-bit: no wrap across replays)
__device__ unsigned long long g_cnt = 0;

__device__ __forceinline__ float fast_sigmoid(float x) {
    return 1.0f / (1.0f + __expf(-x));
}
__device__ __forceinline__ float fast_tanh(float x) {
    float ax = fabsf(x);
    float e  = __expf(-2.0f * ax);
    return copysignf((1.0f - e) / (1.0f + e), x);
}
__device__ __forceinline__ unsigned to_tf32(float f) {
    unsigned r;
    asm("cvt.rna.tf32.f32 %0, %1;" : "=r"(r) : "f"(f));
    return r;
}
__device__ __forceinline__ void mma_tf32(float* c, unsigned a0, unsigned a1,
                                         unsigned a2, unsigned a3,
                                         unsigned b0, unsigned b1) {
    asm("mma.sync.aligned.m16n8k8.row.col.f32.tf32.tf32.f32 "
        "{%0,%1,%2,%3}, {%4,%5,%6,%7}, {%8,%9}, {%0,%1,%2,%3};"
        : "+f"(c[0]), "+f"(c[1]), "+f"(c[2]), "+f"(c[3])
        : "r"(a0), "r"(a1), "r"(a2), "r"(a3), "r"(b0), "r"(b1));
}

// gate-row scatter: n in [0,2048) -> W row
__device__ __forceinline__ int grow_of(int n) {
    return (n & 3) * HDIM + (n >> 4) * 4 + ((n >> 2) & 3);
}

// ======================= Phase 1: xp = x @ W_ih^T =======================
__global__ __launch_bounds__(256, 2)
void lstm_xproj(const float* __restrict__ x, const float* __restrict__ Wih)
{
    extern __shared__ float sm1[];
    float* At = sm1;              // 128 x 68
    float* Bt = sm1 + 128 * 68;   // 128 x 68

    const int tid  = threadIdx.x;
    const int lane = tid & 31;
    const int w    = tid >> 5;
    const int mw   = w & 3;
    const int nw   = w >> 2;
    const int ntile = blockIdx.x & 15;
    const int mtile = blockIdx.x >> 4;
    const int Mb = mtile * 128, Nb = ntile * 128;

    const int lb = tid >> 2;
    const int kc = (tid & 3) * 4;

    float acc[2][8][4];
#pragma unroll
    for (int a = 0; a < 2; ++a)
#pragma unroll
        for (int b = 0; b < 8; ++b)
#pragma unroll
            for (int q = 0; q < 4; ++q) acc[a][b][q] = 0.f;

    for (int ch = 0; ch < 8; ++ch) {
        __syncthreads();
#pragma unroll
        for (int p = 0; p < 2; ++p) {
            int row = p * 64 + lb;
            const float* xs = x + (size_t)(Mb + row) * 512 + ch * 64 + kc;
            unsigned* da = (unsigned*)At + row * 68 + kc;
            int n = Nb + row;
            const float* ws = Wih + (size_t)grow_of(n) * 512 + ch * 64 + kc;
            unsigned* db = (unsigned*)Bt + row * 68 + kc;
#pragma unroll
            for (int c4 = 0; c4 < 4; ++c4) {
                float4 f = *(const float4*)(xs + c4 * 16);
                *(uint4*)(da + c4 * 16) = make_uint4(to_tf32(f.x), to_tf32(f.y),
                                                     to_tf32(f.z), to_tf32(f.w));
                float4 g = *(const float4*)(ws + c4 * 16);
                *(uint4*)(db + c4 * 16) = make_uint4(to_tf32(g.x), to_tf32(g.y),
                                                     to_tf32(g.z), to_tf32(g.w));
            }
        }
        __syncthreads();

        const unsigned* A = (const unsigned*)At;
        const unsigned* B = (const unsigned*)Bt;
#pragma unroll
        for (int i = 0; i < 8; ++i) {
            const int ka = i * 8 + (lane & 3);
            unsigned a[2][4];
#pragma unroll
            for (int m2 = 0; m2 < 2; ++m2) {
                int rb = mw * 32 + m2 * 16 + (lane >> 2);
                a[m2][0] = A[rb * 68 + ka];
                a[m2][1] = A[(rb + 8) * 68 + ka];
                a[m2][2] = A[rb * 68 + ka + 4];
                a[m2][3] = A[(rb + 8) * 68 + ka + 4];
            }
#pragma unroll
            for (int nt = 0; nt < 8; ++nt) {
                int nb = nw * 64 + nt * 8 + (lane >> 2);
                unsigned b0 = B[nb * 68 + ka];
                unsigned b1 = B[nb * 68 + ka + 4];
                mma_tf32(acc[0][nt], a[0][0], a[0][1], a[0][2], a[0][3], b0, b1);
                mma_tf32(acc[1][nt], a[1][0], a[1][1], a[1][2], a[1][3], b0, b1);
            }
        }
    }

#pragma unroll
    for (int m2 = 0; m2 < 2; ++m2) {
#pragma unroll
        for (int nt = 0; nt < 8; ++nt) {
            int row0 = Mb + mw * 32 + m2 * 16 + (lane >> 2);
            int n    = Nb + nw * 64 + nt * 8 + 2 * (lane & 3);
            int t = row0 >> 6, b = row0 & 63;
            size_t idx = (((size_t)t * 128 + (n >> 4)) * 64 + b) * 16 + (n & 15);
            *(float2*)(g_xp + idx)       = make_float2(acc[m2][nt][0], acc[m2][nt][1]);
            *(float2*)(g_xp + idx + 128) = make_float2(acc[m2][nt][2], acc[m2][nt][3]);
        }
    }
}

// ======================= Phase 2: persistent recurrence =======================
// SMEM float offsets
#define HB_OFF   0                      // 8 subtiles x 64 x 68 = 34816
#define RED_OFF  34816                  // 8 x 1536 = 12288
#define BSM_OFF  (RED_OFF + 12288)      // 16
#define SB_OFF   (BSM_OFF + 16)         // ull base0 (8B aligned)
#define SM2_FLOATS (SB_OFF + 4)

__global__ __launch_bounds__(512, 1)
void lstm_rec(const float* __restrict__ Whh,
              const float* __restrict__ bih,
              const float* __restrict__ bhh,
              float* __restrict__ out)
{
    extern __shared__ float sm[];
    float* Hb  = sm + HB_OFF;
    float* Red = sm + RED_OFF;
    float* bsm = sm + BSM_OFF;
    unsigned long long* sbase = (unsigned long long*)(sm + SB_OFF);

    const int tid  = threadIdx.x;
    const int lane = tid & 31;
    const int wid  = tid >> 5;
    const int ct   = blockIdx.x;
    const int mt   = wid & 1;          // batches mt*32..+31
    const int ks   = wid >> 1;         // k subtile 0..7 (64 k each)

    // h staging mapping (512 threads cover 64 x 512)
    const int hb2 = tid >> 8;
    const int lb  = (tid & 255) >> 2;
    const int kc  = (tid & 3) * 4;

    // epilogue mapping (tid < 256)
    const int eb = tid >> 2;
    const int eu = tid & 3;
    float c_state = 0.0f;

    // ---- one-time: Whh B-fragments -> REGISTERS (weight-stationary) ----
    unsigned wreg[8][2][2];
#pragma unroll
    for (int i = 0; i < 8; ++i) {
#pragma unroll
        for (int nt = 0; nt < 2; ++nt) {
            int r = nt * 8 + (lane >> 2);
            int grow = (r & 3) * HDIM + ct * 4 + (r >> 2);
            int k0 = ks * 64 + i * 8 + (lane & 3);
            wreg[i][nt][0] = to_tf32(Whh[(size_t)grow * 512 + k0]);
            wreg[i][nt][1] = to_tf32(Whh[(size_t)grow * 512 + k0 + 4]);
        }
    }
    if (tid < 16) {
        int grow = (tid & 3) * HDIM + ct * 4 + (tid >> 2);
        bsm[tid] = bih[grow] + bhh[grow];
    }
    if (tid == 0) *sbase = *((volatile unsigned long long*)&g_cnt);
    __syncthreads();
    const unsigned long long base0 = *sbase;

    float* hout = out;
    float* cout = out + (size_t)S_LEN * NBATCH * HDIM;

    for (int t = 0; t < S_LEN; ++t) {
        // prefetch x-projection slice (independent of h)
        float4 xpv;
        if (tid < 256)
            xpv = *(const float4*)(g_xp + (((size_t)t * 128 + ct) * 64 + eb) * 16 + eu * 4);

        if (t > 0) {
            // one-hop barrier wait: all 128 arrivals of step t-1 observed
            if (tid == 0) {
                const unsigned long long target = base0 + (unsigned long long)NCTA * t;
                while (*((volatile unsigned long long*)&g_cnt) < target) { }
            }
            __syncthreads();

            // ---- stage full h_{t-1}: 8 subtiles of 64x64, stride 68, tf32 ----
            const float* hbase = hout + (size_t)(t - 1) * (NBATCH * HDIM);
#pragma unroll
            for (int i = 0; i < 4; ++i) {
                int st = hb2 * 4 + i;
                const float* sp = hbase + (size_t)lb * 512 + st * 64 + kc;
                unsigned* dp = (unsigned*)(Hb + st * 4352) + lb * 68 + kc;
#pragma unroll
                for (int c4 = 0; c4 < 4; ++c4) {
                    float4 f = *(const float4*)(sp + c4 * 16);
                    *(uint4*)(dp + c4 * 16) = make_uint4(to_tf32(f.x), to_tf32(f.y),
                                                         to_tf32(f.z), to_tf32(f.w));
                }
            }
            __syncthreads();

            // ---- h GEMM: warp (mt, ks); W from registers ----
            float acc[2][2][4];    // [m2][nt][4]
#pragma unroll
            for (int m2 = 0; m2 < 2; ++m2)
#pragma unroll
                for (int nt = 0; nt < 2; ++nt)
#pragma unroll
                    for (int q = 0; q < 4; ++q) acc[m2][nt][q] = 0.f;

            const unsigned* Ab = (const unsigned*)(Hb + ks * 4352);
#pragma unroll
            for (int i = 0; i < 8; ++i) {
                const int ka = i * 8 + (lane & 3);
#pragma unroll
                for (int m2 = 0; m2 < 2; ++m2) {
                    const int ra = mt * 32 + m2 * 16 + (lane >> 2);
                    unsigned a0 = Ab[ra * 68 + ka];
                    unsigned a1 = Ab[(ra + 8) * 68 + ka];
                    unsigned a2 = Ab[ra * 68 + ka + 4];
                    unsigned a3 = Ab[(ra + 8) * 68 + ka + 4];
                    mma_tf32(acc[m2][0], a0, a1, a2, a3, wreg[i][0][0], wreg[i][0][1]);
                    mma_tf32(acc[m2][1], a0, a1, a2, a3, wreg[i][1][0], wreg[i][1][1]);
                }
            }

            // partials -> Red[ks] : [64][24]
            float* Rp = Red + ks * 1536;
#pragma unroll
            for (int m2 = 0; m2 < 2; ++m2) {
                const int rr = mt * 32 + m2 * 16 + (lane >> 2);
#pragma unroll
                for (int nt = 0; nt < 2; ++nt) {
                    const int cc = nt * 8 + 2 * (lane & 3);
                    *(float2*)(Rp + rr * 24 + cc) =
                        make_float2(acc[m2][nt][0], acc[m2][nt][1]);
                    *(float2*)(Rp + (rr + 8) * 24 + cc) =
                        make_float2(acc[m2][nt][2], acc[m2][nt][3]);
                }
            }
        }

        __syncthreads();

        if (tid < 256) {
            float g[4];
#pragma unroll
            for (int j = 0; j < 4; ++j) g[j] = bsm[eu * 4 + j];
            g[0] += xpv.x; g[1] += xpv.y; g[2] += xpv.z; g[3] += xpv.w;
            if (t > 0) {
#pragma unroll
                for (int s = 0; s < 8; ++s) {
                    const float4 p = *(const float4*)(Red + s * 1536 + eb * 24 + eu * 4);
                    g[0] += p.x; g[1] += p.y; g[2] += p.z; g[3] += p.w;
                }
            }
            float gi = fast_sigmoid(g[0]);
            float gf = fast_sigmoid(g[1]);
            float gg = fast_tanh  (g[2]);
            float go = fast_sigmoid(g[3]);
            c_state = gf * c_state + gi * gg;
            float hval = go * fast_tanh(c_state);

            size_t o = (size_t)t * (NBATCH * HDIM) + (size_t)eb * HDIM + ct * 4 + eu;
            hout[o] = hval;
            cout[o] = c_state;
            __threadfence();
        }

        __syncthreads();   // h_t written + fenced by all writers

        // arrive (monotonic)
        if (tid == 0) atomicAdd(&g_cnt, 1ULL);
    }
}

extern "C" void kernel_launch(void* const* d_in, const int* in_sizes, int n_in,
                              void* d_out, int out_size)
{
    const float* x   = (const float*)d_in[0];
    const float* Wih = (const float*)d_in[1];
    const float* Whh = (const float*)d_in[2];
    const float* bih = (const float*)d_in[3];
    const float* bhh = (const float*)d_in[4];
    float* out = (float*)d_out;

    const int sm1_bytes = 2 * 128 * 68 * 4;          // 69.6 KB
    cudaFuncSetAttribute(lstm_xproj,
                         cudaFuncAttributeMaxDynamicSharedMemorySize, sm1_bytes);
    const int sm2_bytes = SM2_FLOATS * 4;            // ~188.5 KB -> 1 CTA/SM
    cudaFuncSetAttribute(lstm_rec,
                         cudaFuncAttributeMaxDynamicSharedMemorySize, sm2_bytes);

    lstm_xproj<<<16384, 256, sm1_bytes>>>(x, Wih);
    lstm_rec<<<NCTA, 512, sm2_bytes>>>(Whh, bih, bhh, out);
}